// round 3
// baseline (speedup 1.0000x reference)
#include <cuda_runtime.h>
#include <math.h>

// Problem constants (fixed by the dataset)
#define B_ 512
#define T_ 256
#define H_ 512
#define E_ 10
#define V_ 10000
#define C_ 10

// Ping-pong recurrent state in device globals (no allocations allowed)
__device__ float g_h[2][B_ * H_];
__device__ float g_c[2][B_ * H_];

// ---------------------------------------------------------------------------
// Zero-init h0, c0 (buffer 0)
// ---------------------------------------------------------------------------
__global__ void init_state_kernel() {
    int i = blockIdx.x * blockDim.x + threadIdx.x;
    if (i < B_ * H_) {
        g_h[0][i] = 0.0f;
        g_c[0][i] = 0.0f;
    }
}

// ---------------------------------------------------------------------------
// One LSTM timestep, fully fused:
//   z_g = xe_t @ Wgx + h @ Wgh + bg   (and i, f, o)
//   c'  = tanh(z_g)*sig(z_i) + c*sig(z_f)
//   h'  = tanh(c')*sig(z_o)
// Tiling: 32x32 output tile (batch x hidden), all 4 gates per block so the
// elementwise update fuses in-register. BK=32 K-tiles over H.
// Grid: (H/32, B/32) = (16,16) = 256 blocks, 256 threads each.
// ---------------------------------------------------------------------------
#define BM 32
#define BN 32
#define BK 32

__global__ __launch_bounds__(256) void lstm_step_kernel(
    int t, int src,
    const int* __restrict__ x, const float* __restrict__ emb,
    const float* __restrict__ Wgx, const float* __restrict__ Wgh, const float* __restrict__ bg,
    const float* __restrict__ Wix, const float* __restrict__ Wih, const float* __restrict__ bi,
    const float* __restrict__ Wfx, const float* __restrict__ Wfh, const float* __restrict__ bf_,
    const float* __restrict__ Wox, const float* __restrict__ Woh, const float* __restrict__ bo)
{
    const float* __restrict__ h_in = g_h[src];
    const float* __restrict__ c_in = g_c[src];
    float* __restrict__ h_out = g_h[src ^ 1];
    float* __restrict__ c_out = g_c[src ^ 1];

    __shared__ float As[BM][BK];           // h tile
    __shared__ float Bs[4][BK][BN + 1];    // Wh tiles, 4 gates (padded)
    __shared__ float Xs[BM][E_];           // embedded x_t tile
    __shared__ float WxS[4][E_][BN];       // Wx tiles, 4 gates

    const int tx = threadIdx.x % 16;   // micro-col group (2 cols each)
    const int ty = threadIdx.x / 16;   // micro-row group (2 rows each)
    const int bj = blockIdx.x * BN;    // hidden-col base
    const int bb = blockIdx.y * BM;    // batch-row base

    const float* const Wh[4] = {Wgh, Wih, Wfh, Woh};
    const float* const Wx[4] = {Wgx, Wix, Wfx, Wox};

    float acc[4][2][2] = {};

    // ---- x-projection part (K = E = 10) ----
    for (int i = threadIdx.x; i < BM * E_; i += 256) {
        int r = i / E_, e = i % E_;
        int idx = x[(bb + r) * T_ + t];
        // crash-guard: clamp to valid range (no-op for valid tokens)
        idx = min(max(idx, 0), V_ - 1);
        Xs[r][e] = emb[idx * E_ + e];
    }
    #pragma unroll
    for (int g = 0; g < 4; g++) {
        const float* W = Wx[g];
        for (int i = threadIdx.x; i < E_ * BN; i += 256) {
            int e = i / BN, c = i % BN;
            WxS[g][e][c] = W[e * H_ + bj + c];
        }
    }
    __syncthreads();

    #pragma unroll
    for (int e = 0; e < E_; e++) {
        float a0 = Xs[ty * 2 + 0][e];
        float a1 = Xs[ty * 2 + 1][e];
        #pragma unroll
        for (int g = 0; g < 4; g++) {
            float b0 = WxS[g][e][tx * 2 + 0];
            float b1 = WxS[g][e][tx * 2 + 1];
            acc[g][0][0] += a0 * b0; acc[g][0][1] += a0 * b1;
            acc[g][1][0] += a1 * b0; acc[g][1][1] += a1 * b1;
        }
    }
    __syncthreads();

    // ---- recurrent part (K = H = 512) ----
    for (int k0 = 0; k0 < H_; k0 += BK) {
        for (int i = threadIdx.x; i < BM * BK; i += 256) {
            int r = i / BK, c = i % BK;
            As[r][c] = h_in[(bb + r) * H_ + k0 + c];
        }
        #pragma unroll
        for (int g = 0; g < 4; g++) {
            const float* W = Wh[g];
            for (int i = threadIdx.x; i < BK * BN; i += 256) {
                int r = i / BN, c = i % BN;
                Bs[g][r][c] = W[(k0 + r) * H_ + bj + c];
            }
        }
        __syncthreads();

        #pragma unroll
        for (int kk = 0; kk < BK; kk++) {
            float a0 = As[ty * 2 + 0][kk];
            float a1 = As[ty * 2 + 1][kk];
            #pragma unroll
            for (int g = 0; g < 4; g++) {
                float b0 = Bs[g][kk][tx * 2 + 0];
                float b1 = Bs[g][kk][tx * 2 + 1];
                acc[g][0][0] += a0 * b0; acc[g][0][1] += a0 * b1;
                acc[g][1][0] += a1 * b0; acc[g][1][1] += a1 * b1;
            }
        }
        __syncthreads();
    }

    // ---- bias + activations + state update (fused epilogue) ----
    #pragma unroll
    for (int u = 0; u < 2; u++) {
        int brow = bb + ty * 2 + u;
        #pragma unroll
        for (int v = 0; v < 2; v++) {
            int j = bj + tx * 2 + v;
            float zg = acc[0][u][v] + bg[j];
            float zi = acc[1][u][v] + bi[j];
            float zf = acc[2][u][v] + bf_[j];
            float zo = acc[3][u][v] + bo[j];

            float gg = tanhf(zg);
            float ii = 1.0f / (1.0f + __expf(-zi));
            float ff = 1.0f / (1.0f + __expf(-zf));
            float oo = 1.0f / (1.0f + __expf(-zo));

            float cn = gg * ii + c_in[brow * H_ + j] * ff;
            float hn = tanhf(cn) * oo;

            c_out[brow * H_ + j] = cn;
            h_out[brow * H_ + j] = hn;
        }
    }
}

// ---------------------------------------------------------------------------
// Final projection: out[b,c] = h_T[b,:] @ Wph[:,c] + bp[c]   (tiny: 512x10)
// ---------------------------------------------------------------------------
__global__ void proj_kernel(int src, const float* __restrict__ Wph,
                            const float* __restrict__ bp, float* __restrict__ out) {
    int i = blockIdx.x * blockDim.x + threadIdx.x;
    if (i >= B_ * C_) return;
    int b = i / C_;
    int c = i % C_;
    const float* __restrict__ h = g_h[src];
    float acc = bp[c];
    #pragma unroll 8
    for (int k = 0; k < H_; k++) {
        acc += h[b * H_ + k] * Wph[k * C_ + c];
    }
    out[i] = acc;
}

// ---------------------------------------------------------------------------
// Launch: 1 init + 256 dependent step kernels + 1 projection, all on the
// default stream so graph capture records the serial chain.
// ---------------------------------------------------------------------------
extern "C" void kernel_launch(void* const* d_in, const int* in_sizes, int n_in,
                              void* d_out, int out_size) {
    const int* x        = (const int*)d_in[0];       // int32 (JAX downcasts int64)
    const float* emb    = (const float*)d_in[1];
    const float* Wgx    = (const float*)d_in[2];
    const float* Wgh    = (const float*)d_in[3];
    const float* bg     = (const float*)d_in[4];
    const float* Wix    = (const float*)d_in[5];
    const float* Wih    = (const float*)d_in[6];
    const float* bi     = (const float*)d_in[7];
    const float* Wfx    = (const float*)d_in[8];
    const float* Wfh    = (const float*)d_in[9];
    const float* bf_    = (const float*)d_in[10];
    const float* Wox    = (const float*)d_in[11];
    const float* Woh    = (const float*)d_in[12];
    const float* bo     = (const float*)d_in[13];
    const float* Wph    = (const float*)d_in[14];
    const float* bp     = (const float*)d_in[15];
    float* out          = (float*)d_out;

    init_state_kernel<<<(B_ * H_ + 255) / 256, 256>>>();

    dim3 grid(H_ / BN, B_ / BM);  // (16, 16)
    for (int t = 0; t < T_; t++) {
        lstm_step_kernel<<<grid, 256>>>(
            t, t & 1, x, emb,
            Wgx, Wgh, bg, Wix, Wih, bi, Wfx, Wfh, bf_, Wox, Woh, bo);
    }

    // After t=255 (odd), the freshest h lives in buffer 0.
    proj_kernel<<<(B_ * C_ + 255) / 256, 256>>>(0, Wph, bp, out);
}

// round 4
// speedup vs baseline: 2.0340x; 2.0340x over previous
#include <cuda_runtime.h>
#include <math.h>
#include <stdint.h>

// Problem constants (fixed by the dataset)
#define B_ 512
#define T_ 256
#define H_ 512
#define E_ 10
#define V_ 10000
#define C_ 10

// GEMM tiling
#define BM 32      // batch rows per block
#define BN 32      // hidden cols per gate per block
#define BK 32      // k-tile
#define NT 128     // threads per block

// Ping-pong recurrent state in device globals (no allocations allowed)
__device__ float g_h[2][B_ * H_];
__device__ float g_c[2][B_ * H_];

__global__ void init_state_kernel() {
    int i = blockIdx.x * blockDim.x + threadIdx.x;
    if (i < B_ * H_) {
        g_h[0][i] = 0.0f;
        g_c[0][i] = 0.0f;
    }
}

__device__ __forceinline__ void cp16(void* smem_dst, const void* gmem_src) {
    uint32_t s = (uint32_t)__cvta_generic_to_shared(smem_dst);
    asm volatile("cp.async.cg.shared.global [%0], [%1], 16;" :: "r"(s), "l"(gmem_src));
}

// ---------------------------------------------------------------------------
// One LSTM timestep, fully fused, double-buffered cp.async pipeline.
// Block tile: 32 batch rows x 32 hidden cols x 4 gates. 128 threads,
// each thread owns a 2-row x 4-col x 4-gate micro-tile (32 accumulators).
// Grid: (H/32, B/32) = (16,16) = 256 blocks; 2 blocks resident per SM.
// ---------------------------------------------------------------------------
__global__ __launch_bounds__(NT) void lstm_step_kernel(
    int t, int src,
    const int* __restrict__ x, const float* __restrict__ emb,
    const float* __restrict__ Wgx, const float* __restrict__ Wgh, const float* __restrict__ bg,
    const float* __restrict__ Wix, const float* __restrict__ Wih, const float* __restrict__ bi,
    const float* __restrict__ Wfx, const float* __restrict__ Wfh, const float* __restrict__ bf_,
    const float* __restrict__ Wox, const float* __restrict__ Woh, const float* __restrict__ bo)
{
    __shared__ float As[2][BM][BK];          // h tile       (8 KB)
    __shared__ float Bs[2][4][BK][BN];       // Wh tiles     (32 KB)
    __shared__ float Xs[BM][E_];             // embedded x_t (1.25 KB)
    __shared__ float WxS[4][E_][BN];         // Wx tiles     (5 KB)

    const int tid = threadIdx.x;
    const int tx = tid & 7;        // 8 groups -> 4 cols each
    const int ty = tid >> 3;       // 16 groups -> 2 rows each
    const int bj = blockIdx.x * BN;
    const int bb = blockIdx.y * BM;

    const float* __restrict__ h_in = g_h[src];
    const float* __restrict__ c_in = g_c[src];
    float* __restrict__ h_out = g_h[src ^ 1];
    float* __restrict__ c_out = g_c[src ^ 1];

    // ---- stage x-projection operands into smem ----
    for (int i = tid; i < BM * E_; i += NT) {
        int r = i / E_, e = i % E_;
        int idx = x[(bb + r) * T_ + t];
        idx = min(max(idx, 0), V_ - 1);
        Xs[r][e] = emb[idx * E_ + e];
    }
    {
        const float* const Wx[4] = {Wgx, Wix, Wfx, Wox};
        #pragma unroll
        for (int g = 0; g < 4; g++) {
            const float* W = Wx[g];
            for (int i = tid; i < E_ * BN; i += NT) {
                int e = i / BN, c = i % BN;
                WxS[g][e][c] = W[e * H_ + bj + c];
            }
        }
    }

    float acc[4][2][4];
    #pragma unroll
    for (int g = 0; g < 4; g++)
        #pragma unroll
        for (int u = 0; u < 2; u++)
            #pragma unroll
            for (int v = 0; v < 4; v++) acc[g][u][v] = 0.0f;

    // ---- cp.async tile loader (A + 4 gate B tiles, all float4) ----
    auto load_tile = [&](int buf, int k0) {
        #pragma unroll
        for (int half = 0; half < 2; half++) {
            int idx = tid + half * NT;
            int r = idx >> 3, c4 = (idx & 7) * 4;
            cp16(&As[buf][r][c4], &h_in[(bb + r) * H_ + k0 + c4]);
        }
        const float* const Wh[4] = {Wgh, Wih, Wfh, Woh};
        #pragma unroll
        for (int g = 0; g < 4; g++) {
            #pragma unroll
            for (int half = 0; half < 2; half++) {
                int idx = tid + half * NT;
                int k = idx >> 3, c4 = (idx & 7) * 4;
                cp16(&Bs[buf][g][k][c4], &Wh[g][(k0 + k) * H_ + bj + c4]);
            }
        }
        asm volatile("cp.async.commit_group;");
    };

    // prologue: kick off tile 0
    load_tile(0, 0);

    // x-projection math (overlaps with first tile's copies)
    __syncthreads();   // Xs/WxS ready
    #pragma unroll
    for (int e = 0; e < E_; e++) {
        float a0 = Xs[2 * ty + 0][e];
        float a1 = Xs[2 * ty + 1][e];
        #pragma unroll
        for (int g = 0; g < 4; g++) {
            float4 b = *(const float4*)&WxS[g][e][4 * tx];
            acc[g][0][0] += a0 * b.x; acc[g][0][1] += a0 * b.y;
            acc[g][0][2] += a0 * b.z; acc[g][0][3] += a0 * b.w;
            acc[g][1][0] += a1 * b.x; acc[g][1][1] += a1 * b.y;
            acc[g][1][2] += a1 * b.z; acc[g][1][3] += a1 * b.w;
        }
    }

    // ---- recurrent GEMM mainloop (K = 512, 16 double-buffered tiles) ----
    #pragma unroll 1
    for (int kt = 0; kt < H_ / BK; kt++) {
        asm volatile("cp.async.wait_group 0;" ::: "memory");
        __syncthreads();
        if (kt + 1 < H_ / BK) load_tile((kt + 1) & 1, (kt + 1) * BK);

        const int buf = kt & 1;
        #pragma unroll 8
        for (int k = 0; k < BK; k++) {
            float a0 = As[buf][2 * ty + 0][k];
            float a1 = As[buf][2 * ty + 1][k];
            #pragma unroll
            for (int g = 0; g < 4; g++) {
                float4 b = *(const float4*)&Bs[buf][g][k][4 * tx];
                acc[g][0][0] += a0 * b.x; acc[g][0][1] += a0 * b.y;
                acc[g][0][2] += a0 * b.z; acc[g][0][3] += a0 * b.w;
                acc[g][1][0] += a1 * b.x; acc[g][1][1] += a1 * b.y;
                acc[g][1][2] += a1 * b.z; acc[g][1][3] += a1 * b.w;
            }
        }
    }

    // ---- fused epilogue: bias + activations + state update ----
    const int j0 = bj + 4 * tx;
    float4 bgv = *(const float4*)&bg[j0];
    float4 biv = *(const float4*)&bi[j0];
    float4 bfv = *(const float4*)&bf_[j0];
    float4 bov = *(const float4*)&bo[j0];
    float bgs[4] = {bgv.x, bgv.y, bgv.z, bgv.w};
    float bis[4] = {biv.x, biv.y, biv.z, biv.w};
    float bfs[4] = {bfv.x, bfv.y, bfv.z, bfv.w};
    float bos[4] = {bov.x, bov.y, bov.z, bov.w};

    #pragma unroll
    for (int u = 0; u < 2; u++) {
        int row = bb + 2 * ty + u;
        float4 cv = *(const float4*)&c_in[row * H_ + j0];
        float cold[4] = {cv.x, cv.y, cv.z, cv.w};
        float4 cnew, hnew;
        float cn[4], hn[4];
        #pragma unroll
        for (int v = 0; v < 4; v++) {
            float zg = acc[0][u][v] + bgs[v];
            float zi = acc[1][u][v] + bis[v];
            float zf = acc[2][u][v] + bfs[v];
            float zo = acc[3][u][v] + bos[v];

            float gg = tanhf(zg);
            float ii = 1.0f / (1.0f + __expf(-zi));
            float ff = 1.0f / (1.0f + __expf(-zf));
            float oo = 1.0f / (1.0f + __expf(-zo));

            cn[v] = gg * ii + cold[v] * ff;
            hn[v] = tanhf(cn[v]) * oo;
        }
        cnew.x = cn[0]; cnew.y = cn[1]; cnew.z = cn[2]; cnew.w = cn[3];
        hnew.x = hn[0]; hnew.y = hn[1]; hnew.z = hn[2]; hnew.w = hn[3];
        *(float4*)&c_out[row * H_ + j0] = cnew;
        *(float4*)&h_out[row * H_ + j0] = hnew;
    }
}

// ---------------------------------------------------------------------------
// Final projection: out[b,c] = h_T[b,:] @ Wph[:,c] + bp[c]   (tiny: 512x10)
// ---------------------------------------------------------------------------
__global__ void proj_kernel(int src, const float* __restrict__ Wph,
                            const float* __restrict__ bp, float* __restrict__ out) {
    int i = blockIdx.x * blockDim.x + threadIdx.x;
    if (i >= B_ * C_) return;
    int b = i / C_;
    int c = i % C_;
    const float* __restrict__ h = g_h[src];
    float acc = bp[c];
    #pragma unroll 8
    for (int k = 0; k < H_; k++) {
        acc += h[b * H_ + k] * Wph[k * C_ + c];
    }
    out[i] = acc;
}

// ---------------------------------------------------------------------------
// Launch: 1 init + 256 dependent step kernels + 1 projection on one stream.
// ---------------------------------------------------------------------------
extern "C" void kernel_launch(void* const* d_in, const int* in_sizes, int n_in,
                              void* d_out, int out_size) {
    const int* x        = (const int*)d_in[0];       // int32 (JAX downcasts int64)
    const float* emb    = (const float*)d_in[1];
    const float* Wgx    = (const float*)d_in[2];
    const float* Wgh    = (const float*)d_in[3];
    const float* bg     = (const float*)d_in[4];
    const float* Wix    = (const float*)d_in[5];
    const float* Wih    = (const float*)d_in[6];
    const float* bi     = (const float*)d_in[7];
    const float* Wfx    = (const float*)d_in[8];
    const float* Wfh    = (const float*)d_in[9];
    const float* bf_    = (const float*)d_in[10];
    const float* Wox    = (const float*)d_in[11];
    const float* Woh    = (const float*)d_in[12];
    const float* bo     = (const float*)d_in[13];
    const float* Wph    = (const float*)d_in[14];
    const float* bp     = (const float*)d_in[15];
    float* out          = (float*)d_out;

    init_state_kernel<<<(B_ * H_ + 255) / 256, 256>>>();

    dim3 grid(H_ / BN, B_ / BM);  // (16, 16)
    for (int t = 0; t < T_; t++) {
        lstm_step_kernel<<<grid, NT>>>(
            t, t & 1, x, emb,
            Wgx, Wgh, bg, Wix, Wih, bi, Wfx, Wfh, bf_, Wox, Woh, bo);
    }

    // After t=255 (odd), the freshest h lives in buffer 0.
    proj_kernel<<<(B_ * C_ + 255) / 256, 256>>>(0, Wph, bp, out);
}

// round 5
// speedup vs baseline: 4.4667x; 2.1960x over previous
#include <cuda_runtime.h>
#include <cuda_bf16.h>
#include <math.h>
#include <stdint.h>

// Problem constants
#define B_ 512
#define T_ 256
#define H_ 512
#define E_ 10
#define V_ 10000
#define C_ 10
#define NGATE 4
#define N_TOT (NGATE * H_)   // 2048 = concat gate columns [g|i|f|o]

// ---------------------------------------------------------------------------
// Device-global state & scratch (no allocations allowed)
// ---------------------------------------------------------------------------
__device__ float g_h[B_ * H_];
__device__ float g_c[B_ * H_];
__device__ __nv_bfloat16 g_hhi[B_ * H_];
__device__ __nv_bfloat16 g_hlo[B_ * H_];
__device__ __nv_bfloat16 g_Wthi[N_TOT * H_];   // W^T split-hi: [n][k]
__device__ __nv_bfloat16 g_Wtlo[N_TOT * H_];   // W^T split-lo
__device__ float g_z[B_ * N_TOT];              // gate pre-activations

// ---------------------------------------------------------------------------
// One-time (per launch) weight transpose + bf16 hi/lo split.
// Wt[g*512 + j][k] = Wh_g[k][j]
// ---------------------------------------------------------------------------
__global__ void prep_weights_kernel(
    const float* __restrict__ Wgh, const float* __restrict__ Wih,
    const float* __restrict__ Wfh, const float* __restrict__ Woh)
{
    __shared__ float tile[32][33];
    const float* const W[4] = {Wgh, Wih, Wfh, Woh};
    const int g = blockIdx.z;
    const int j0 = blockIdx.x * 32;
    const int k0 = blockIdx.y * 32;
    const int tx = threadIdx.x, ty = threadIdx.y;

    tile[ty][tx] = W[g][(k0 + ty) * H_ + j0 + tx];
    __syncthreads();

    float w = tile[tx][ty];                       // = W[k0+tx][j0+ty]
    __nv_bfloat16 hi = __float2bfloat16(w);
    __nv_bfloat16 lo = __float2bfloat16(w - __bfloat162float(hi));
    int n = g * H_ + j0 + ty;
    g_Wthi[n * H_ + k0 + tx] = hi;
    g_Wtlo[n * H_ + k0 + tx] = lo;
}

__global__ void init_state_kernel() {
    int i = blockIdx.x * blockDim.x + threadIdx.x;
    if (i < B_ * H_) {
        g_h[i] = 0.0f;
        g_c[i] = 0.0f;
        g_hhi[i] = __float2bfloat16(0.0f);
        g_hlo[i] = __float2bfloat16(0.0f);
    }
}

// ---------------------------------------------------------------------------
// cp.async helper
// ---------------------------------------------------------------------------
__device__ __forceinline__ void cp16(void* smem_dst, const void* gmem_src) {
    uint32_t s = (uint32_t)__cvta_generic_to_shared(smem_dst);
    asm volatile("cp.async.cg.shared.global [%0], [%1], 16;" :: "r"(s), "l"(gmem_src));
}

__device__ __forceinline__ void mma_bf16(
    float c[4], const uint32_t a[4], uint32_t b0, uint32_t b1)
{
    asm volatile(
        "mma.sync.aligned.m16n8k16.row.col.f32.bf16.bf16.f32 "
        "{%0,%1,%2,%3}, {%4,%5,%6,%7}, {%8,%9}, {%0,%1,%2,%3};"
        : "+f"(c[0]), "+f"(c[1]), "+f"(c[2]), "+f"(c[3])
        : "r"(a[0]), "r"(a[1]), "r"(a[2]), "r"(a[3]), "r"(b0), "r"(b1));
}

// ---------------------------------------------------------------------------
// Recurrent GEMM: z[512 x 2048] = h[512 x 512] @ Wt^T, split-bf16 3-term MMA.
// Block tile 64(M) x 128(N), 8 warps (warp tile 16x64), k-chunks of 32,
// cp.async double-buffered. Grid (2048/128, 512/64) = (16, 8) = 128 blocks.
// ---------------------------------------------------------------------------
#define GBM 64
#define GBN 128
#define GKC 32
#define APAD 40                     // padded k-row (bf16 elems): conflict-free
#define GEMM_THREADS 256
#define A_ELEMS (2 * 2 * GBM * APAD)    // [buf][hi/lo][row][col]
#define B_ELEMS (2 * 2 * GBN * APAD)
#define GEMM_SMEM_BYTES ((A_ELEMS + B_ELEMS) * 2)

__global__ void __launch_bounds__(GEMM_THREADS) gemm_step_kernel() {
    extern __shared__ __nv_bfloat16 sm[];
    __nv_bfloat16* const Asm = sm;
    __nv_bfloat16* const Bsm = sm + A_ELEMS;

    const int tid = threadIdx.x;
    const int bn = blockIdx.x * GBN;
    const int bb = blockIdx.y * GBM;
    const int w = tid >> 5;
    const int lane = tid & 31;
    const int gid = lane >> 2;     // 0..7
    const int tig = lane & 3;      // 0..3
    const int wm = (w >> 1) * 16;  // warp m-offset within block tile
    const int wn = (w & 1) * 64;   // warp n-offset

    auto aoff = [&](int buf, int hl, int r, int c) {
        return ((buf * 2 + hl) * GBM + r) * APAD + c;
    };
    auto boff = [&](int buf, int hl, int r, int c) {
        return ((buf * 2 + hl) * GBN + r) * APAD + c;
    };

    auto load_chunk = [&](int buf, int k0) {
        int r = tid >> 2, s = (tid & 3) * 8;
        cp16(&Asm[aoff(buf, 0, r, s)], &g_hhi[(bb + r) * H_ + k0 + s]);
        cp16(&Asm[aoff(buf, 1, r, s)], &g_hlo[(bb + r) * H_ + k0 + s]);
        #pragma unroll
        for (int half = 0; half < 2; half++) {
            int idx2 = tid + half * GEMM_THREADS;
            int br = idx2 >> 2, bs = (idx2 & 3) * 8;
            cp16(&Bsm[boff(buf, 0, br, bs)], &g_Wthi[(bn + br) * H_ + k0 + bs]);
            cp16(&Bsm[boff(buf, 1, br, bs)], &g_Wtlo[(bn + br) * H_ + k0 + bs]);
        }
        asm volatile("cp.async.commit_group;");
    };

    float acc[8][4];
    #pragma unroll
    for (int nf = 0; nf < 8; nf++)
        #pragma unroll
        for (int v = 0; v < 4; v++) acc[nf][v] = 0.0f;

    load_chunk(0, 0);

    const int NCH = H_ / GKC;   // 16
    #pragma unroll 1
    for (int kt = 0; kt < NCH; kt++) {
        asm volatile("cp.async.wait_group 0;" ::: "memory");
        __syncthreads();
        if (kt + 1 < NCH) load_chunk((kt + 1) & 1, (kt + 1) * GKC);

        const int buf = kt & 1;
        #pragma unroll
        for (int kk = 0; kk < GKC; kk += 16) {
            uint32_t ahi[4], alo[4];
            const int ar0 = wm + gid, ac0 = kk + 2 * tig;
            ahi[0] = *(const uint32_t*)&Asm[aoff(buf, 0, ar0,     ac0)];
            ahi[1] = *(const uint32_t*)&Asm[aoff(buf, 0, ar0 + 8, ac0)];
            ahi[2] = *(const uint32_t*)&Asm[aoff(buf, 0, ar0,     ac0 + 8)];
            ahi[3] = *(const uint32_t*)&Asm[aoff(buf, 0, ar0 + 8, ac0 + 8)];
            alo[0] = *(const uint32_t*)&Asm[aoff(buf, 1, ar0,     ac0)];
            alo[1] = *(const uint32_t*)&Asm[aoff(buf, 1, ar0 + 8, ac0)];
            alo[2] = *(const uint32_t*)&Asm[aoff(buf, 1, ar0,     ac0 + 8)];
            alo[3] = *(const uint32_t*)&Asm[aoff(buf, 1, ar0 + 8, ac0 + 8)];

            #pragma unroll
            for (int nf = 0; nf < 8; nf++) {
                const int brow = wn + nf * 8 + gid;
                uint32_t bhi0 = *(const uint32_t*)&Bsm[boff(buf, 0, brow, ac0)];
                uint32_t bhi1 = *(const uint32_t*)&Bsm[boff(buf, 0, brow, ac0 + 8)];
                uint32_t blo0 = *(const uint32_t*)&Bsm[boff(buf, 1, brow, ac0)];
                uint32_t blo1 = *(const uint32_t*)&Bsm[boff(buf, 1, brow, ac0 + 8)];
                mma_bf16(acc[nf], ahi, bhi0, bhi1);   // hi*hi
                mma_bf16(acc[nf], ahi, blo0, blo1);   // hi*lo
                mma_bf16(acc[nf], alo, bhi0, bhi1);   // lo*hi
            }
        }
        __syncthreads();
    }

    // store z
    const int row0 = bb + wm + gid;
    #pragma unroll
    for (int nf = 0; nf < 8; nf++) {
        const int col = bn + wn + nf * 8 + 2 * tig;
        float2 v01 = make_float2(acc[nf][0], acc[nf][1]);
        float2 v23 = make_float2(acc[nf][2], acc[nf][3]);
        *(float2*)&g_z[row0 * N_TOT + col]       = v01;
        *(float2*)&g_z[(row0 + 8) * N_TOT + col] = v23;
    }
}

// ---------------------------------------------------------------------------
// Pointwise: z += x-projection + bias, activations, c/h update, h hi/lo split.
// Grid: 512 blocks (one batch row), 512 threads (one hidden unit).
// ---------------------------------------------------------------------------
__global__ void __launch_bounds__(512) pointwise_kernel(
    int t, const int* __restrict__ x, const float* __restrict__ emb,
    const float* __restrict__ Wgx, const float* __restrict__ Wix,
    const float* __restrict__ Wfx, const float* __restrict__ Wox,
    const float* __restrict__ bg, const float* __restrict__ bi,
    const float* __restrict__ bf_, const float* __restrict__ bo)
{
    __shared__ float xe[E_];
    const int b = blockIdx.x;
    const int j = threadIdx.x;
    if (j < E_) {
        int idx = x[b * T_ + t];
        idx = min(max(idx, 0), V_ - 1);   // crash-guard (no-op for valid tokens)
        xe[j] = emb[idx * E_ + j];
    }
    __syncthreads();

    float zg = g_z[b * N_TOT + 0 * H_ + j] + bg[j];
    float zi = g_z[b * N_TOT + 1 * H_ + j] + bi[j];
    float zf = g_z[b * N_TOT + 2 * H_ + j] + bf_[j];
    float zo = g_z[b * N_TOT + 3 * H_ + j] + bo[j];

    #pragma unroll
    for (int e = 0; e < E_; e++) {
        float xv = xe[e];
        zg += xv * Wgx[e * H_ + j];
        zi += xv * Wix[e * H_ + j];
        zf += xv * Wfx[e * H_ + j];
        zo += xv * Wox[e * H_ + j];
    }

    float gg = tanhf(zg);
    float ii = 1.0f / (1.0f + __expf(-zi));
    float ff = 1.0f / (1.0f + __expf(-zf));
    float oo = 1.0f / (1.0f + __expf(-zo));

    float cn = gg * ii + g_c[b * H_ + j] * ff;
    float hn = tanhf(cn) * oo;

    g_c[b * H_ + j] = cn;
    g_h[b * H_ + j] = hn;
    __nv_bfloat16 hi = __float2bfloat16(hn);
    g_hhi[b * H_ + j] = hi;
    g_hlo[b * H_ + j] = __float2bfloat16(hn - __bfloat162float(hi));
}

// ---------------------------------------------------------------------------
// Final projection: out[b,c] = h_T[b,:] @ Wph[:,c] + bp[c]
// ---------------------------------------------------------------------------
__global__ void proj_kernel(const float* __restrict__ Wph,
                            const float* __restrict__ bp, float* __restrict__ out) {
    int i = blockIdx.x * blockDim.x + threadIdx.x;
    if (i >= B_ * C_) return;
    int b = i / C_;
    int c = i % C_;
    float acc = bp[c];
    #pragma unroll 8
    for (int k = 0; k < H_; k++) {
        acc += g_h[b * H_ + k] * Wph[k * C_ + c];
    }
    out[i] = acc;
}

// ---------------------------------------------------------------------------
// Launch sequence (graph-capturable, single stream)
// ---------------------------------------------------------------------------
extern "C" void kernel_launch(void* const* d_in, const int* in_sizes, int n_in,
                              void* d_out, int out_size) {
    const int* x        = (const int*)d_in[0];       // int32 (JAX downcasts int64)
    const float* emb    = (const float*)d_in[1];
    const float* Wgx    = (const float*)d_in[2];
    const float* Wgh    = (const float*)d_in[3];
    const float* bg     = (const float*)d_in[4];
    const float* Wix    = (const float*)d_in[5];
    const float* Wih    = (const float*)d_in[6];
    const float* bi     = (const float*)d_in[7];
    const float* Wfx    = (const float*)d_in[8];
    const float* Wfh    = (const float*)d_in[9];
    const float* bf_    = (const float*)d_in[10];
    const float* Wox    = (const float*)d_in[11];
    const float* Woh    = (const float*)d_in[12];
    const float* bo     = (const float*)d_in[13];
    const float* Wph    = (const float*)d_in[14];
    const float* bp     = (const float*)d_in[15];
    float* out          = (float*)d_out;

    static bool attr_set = false;
    if (!attr_set) {
        cudaFuncSetAttribute(gemm_step_kernel,
                             cudaFuncAttributeMaxDynamicSharedMemorySize,
                             GEMM_SMEM_BYTES);
        attr_set = true;
    }

    // one-time (per replay) prep: transpose + split weights, zero state
    {
        dim3 tgrid(H_ / 32, H_ / 32, NGATE);
        dim3 tblk(32, 32);
        prep_weights_kernel<<<tgrid, tblk>>>(Wgh, Wih, Wfh, Woh);
    }
    init_state_kernel<<<(B_ * H_ + 255) / 256, 256>>>();

    dim3 ggrid(N_TOT / GBN, B_ / GBM);   // (16, 8)
    for (int t = 0; t < T_; t++) {
        gemm_step_kernel<<<ggrid, GEMM_THREADS, GEMM_SMEM_BYTES>>>();
        pointwise_kernel<<<B_, H_>>>(t, x, emb, Wgx, Wix, Wfx, Wox,
                                     bg, bi, bf_, bo);
    }

    proj_kernel<<<(B_ * C_ + 255) / 256, 256>>>(Wph, bp, out);
}